// round 13
// baseline (speedup 1.0000x reference)
#include <cuda_runtime.h>
#include <cstdint>

// DCT per 8x8 patch == out(N,64) = X(N,64) @ (C ⊗ C), separable two-pass,
// 1024 FFMA-imm per strip. R13: one-warp CTA (R12 winner) processing TWO
// 32-strip tiles straight-line with double-buffered cp.async: tile B's DRAM
// latency hides under tile A's compute+store. One latency wait per 2 tiles.

#define THREADS     32
#define TILE_STRIPS 32
#define TILE_F4     (TILE_STRIPS * 16)   // 512 float4 per tile in gmem
#define PAD_F4      (TILE_STRIPS * 17)   // 544 float4 per padded smem buffer

#define DCT_TABLE(CT)                                                                  \
    const float CT[8][8] = {                                                           \
        {0.353553391f, 0.353553391f, 0.353553391f, 0.353553391f,                       \
         0.353553391f, 0.353553391f, 0.353553391f, 0.353553391f},                      \
        {0.490392640f, 0.415734806f, 0.277785117f, 0.097545161f,                       \
         -0.097545161f, -0.277785117f, -0.415734806f, -0.490392640f},                  \
        {0.461939766f, 0.191341716f, -0.191341716f, -0.461939766f,                     \
         -0.461939766f, -0.191341716f, 0.191341716f, 0.461939766f},                    \
        {0.415734806f, -0.097545161f, -0.490392640f, -0.277785117f,                    \
         0.277785117f, 0.490392640f, 0.097545161f, -0.415734806f},                     \
        {0.353553391f, -0.353553391f, -0.353553391f, 0.353553391f,                     \
         0.353553391f, -0.353553391f, -0.353553391f, 0.353553391f},                    \
        {0.277785117f, -0.490392640f, 0.097545161f, 0.415734806f,                      \
         -0.415734806f, -0.097545161f, 0.490392640f, -0.277785117f},                   \
        {0.191341716f, -0.461939766f, 0.461939766f, -0.191341716f,                     \
         -0.191341716f, 0.461939766f, -0.461939766f, 0.191341716f},                    \
        {0.097545161f, -0.277785117f, 0.415734806f, -0.490392640f,                     \
         0.490392640f, -0.415734806f, 0.277785117f, -0.097545161f}};

__device__ __forceinline__ void cp_async16(float4* smem_dst, const float4* gsrc)
{
    uint32_t s = (uint32_t)__cvta_generic_to_shared(smem_dst);
    asm volatile("cp.async.cg.shared.global [%0], [%1], 16;\n" :: "r"(s), "l"(gsrc));
}
__device__ __forceinline__ void cp_commit() { asm volatile("cp.async.commit_group;\n" ::: "memory"); }
__device__ __forceinline__ void cp_wait1()  { asm volatile("cp.async.wait_group 1;\n" ::: "memory"); }
__device__ __forceinline__ void cp_wait0()  { asm volatile("cp.async.wait_group 0;\n" ::: "memory"); }

__device__ __forceinline__ uint64_t mk_evict_first_policy()
{
    uint64_t pol;
    asm("createpolicy.fractional.L2::evict_first.b64 %0, 1.0;" : "=l"(pol));
    return pol;
}
__device__ __forceinline__ void stg128_ef(float4* gdst, float4 v, uint64_t pol)
{
    asm volatile("st.global.L2::cache_hint.v4.f32 [%0], {%1, %2, %3, %4}, %5;\n"
                 :: "l"(gdst), "f"(v.x), "f"(v.y), "f"(v.z), "f"(v.w), "l"(pol)
                 : "memory");
}

// Transform the strip at sp (16 padded float4) in place, then write the
// tile buffer back to gmem coalesced.
__device__ __forceinline__ void transform_and_store(float4* buf, float4* sp,
                                                    float4* gout, int t, int cslot,
                                                    uint64_t pol)
{
    float x[64];
#pragma unroll
    for (int k = 0; k < 16; ++k) {
        float4 v = sp[k];
        x[4 * k + 0] = v.x; x[4 * k + 1] = v.y;
        x[4 * k + 2] = v.z; x[4 * k + 3] = v.w;
    }

    DCT_TABLE(CT);
#pragma unroll
    for (int u = 0; u < 8; ++u) {
        float tr[8];
#pragma unroll
        for (int j = 0; j < 8; ++j) {
            float a = x[u * 8 + 0] * CT[0][j];
#pragma unroll
            for (int v = 1; v < 8; ++v) a = fmaf(x[u * 8 + v], CT[v][j], a);
            tr[j] = a;
        }
#pragma unroll
        for (int j = 0; j < 8; ++j) x[u * 8 + j] = tr[j];
    }
#pragma unroll
    for (int r = 0; r < 8; ++r) {
        float o[8];
#pragma unroll
        for (int j = 0; j < 8; ++j) {
            float a = x[0 * 8 + j] * CT[0][r];
#pragma unroll
            for (int u = 1; u < 8; ++u) a = fmaf(x[u * 8 + j], CT[u][r], a);
            o[j] = a;
        }
        sp[2 * r + 0] = make_float4(o[0], o[1], o[2], o[3]);
        sp[2 * r + 1] = make_float4(o[4], o[5], o[6], o[7]);
    }
    __syncwarp();

#pragma unroll
    for (int k = 0; k < 16; ++k)
        stg128_ef(&gout[k * THREADS + t], buf[2 * k * 17 + cslot], pol);
}

__global__ __launch_bounds__(THREADS)
void dct_warp2_kernel(const float4* __restrict__ in4, float4* __restrict__ out4,
                      int ntiles)
{
    __shared__ float4 smA[PAD_F4];
    __shared__ float4 smB[PAD_F4];
    const int t = threadIdx.x;
    const int cslot = (t >> 4) * 17 + (t & 15);

    const int tileA = 2 * blockIdx.x;
    const int tileB = tileA + 1;
    const bool hasB = (tileB < ntiles);

    const float4* gA = in4 + (size_t)tileA * TILE_F4;

    // Issue tile A loads, then tile B loads — two groups in flight.
#pragma unroll
    for (int k = 0; k < 16; ++k)
        cp_async16(&smA[2 * k * 17 + cslot], &gA[k * THREADS + t]);
    cp_commit();

    if (hasB) {
        const float4* gB = in4 + (size_t)tileB * TILE_F4;
#pragma unroll
        for (int k = 0; k < 16; ++k)
            cp_async16(&smB[2 * k * 17 + cslot], &gB[k * THREADS + t]);
    }
    cp_commit();

    const uint64_t pol = mk_evict_first_policy();

    // Tile A: wait until only B's group is pending, compute+store.
    cp_wait1();
    __syncwarp();
    transform_and_store(smA, smA + t * 17, out4 + (size_t)tileA * TILE_F4,
                        t, cslot, pol);

    // Tile B: its DRAM latency was hidden under A's compute+store.
    if (hasB) {
        cp_wait0();
        __syncwarp();
        transform_and_store(smB, smB + t * 17, out4 + (size_t)tileB * TILE_F4,
                            t, cslot, pol);
    }
}

// Tail (strip count not divisible by 32): direct per-thread path, tiny.
__global__ void dct_tail_kernel(const float4* __restrict__ in4,
                                float4* __restrict__ out4,
                                int first_strip, int nstrips)
{
    int strip = first_strip + blockIdx.x * blockDim.x + threadIdx.x;
    if (strip >= nstrips) return;
    float x[64];
    const float4* ip = in4 + (size_t)strip * 16;
#pragma unroll
    for (int k = 0; k < 16; ++k) {
        float4 v = ip[k];
        x[4 * k + 0] = v.x; x[4 * k + 1] = v.y;
        x[4 * k + 2] = v.z; x[4 * k + 3] = v.w;
    }
    DCT_TABLE(CT);
#pragma unroll
    for (int u = 0; u < 8; ++u) {
        float tr[8];
#pragma unroll
        for (int j = 0; j < 8; ++j) {
            float a = x[u * 8 + 0] * CT[0][j];
#pragma unroll
            for (int v = 1; v < 8; ++v) a = fmaf(x[u * 8 + v], CT[v][j], a);
            tr[j] = a;
        }
#pragma unroll
        for (int j = 0; j < 8; ++j) x[u * 8 + j] = tr[j];
    }
    float4* op = out4 + (size_t)strip * 16;
#pragma unroll
    for (int r = 0; r < 8; ++r) {
        float o[8];
#pragma unroll
        for (int j = 0; j < 8; ++j) {
            float a = x[0 * 8 + j] * CT[0][r];
#pragma unroll
            for (int u = 1; u < 8; ++u) a = fmaf(x[u * 8 + j], CT[u][r], a);
            o[j] = a;
        }
        op[2 * r + 0] = make_float4(o[0], o[1], o[2], o[3]);
        op[2 * r + 1] = make_float4(o[4], o[5], o[6], o[7]);
    }
}

extern "C" void kernel_launch(void* const* d_in, const int* in_sizes, int n_in,
                              void* d_out, int out_size)
{
    const float4* in4 = (const float4*)d_in[0];  // (8,3,1024,1024) fp32 contiguous
    float4* out4      = (float4*)d_out;

    int nstrips = in_sizes[0] / 64;              // 393216 on bench shape
    int ntiles  = nstrips / TILE_STRIPS;         // 12288

    if (ntiles > 0) {
        int grid = (ntiles + 1) / 2;             // 2 tiles per warp-CTA
        dct_warp2_kernel<<<grid, THREADS>>>(in4, out4, ntiles);
    }
    int rem = nstrips - ntiles * TILE_STRIPS;
    if (rem > 0)
        dct_tail_kernel<<<(rem + 127) / 128, 128>>>(in4, out4,
                                                    ntiles * TILE_STRIPS, nstrips);
}